// round 6
// baseline (speedup 1.0000x reference)
#include <cuda_runtime.h>

// Problem constants
#define BTOT   2048
#define TLEN   512
#define HDIM   64
#define G4     256          // 4*H gates
#define BB     14           // batches per block
#define HB     7            // batches per group (two groups per block)
#define XC     128          // x chunk length cached in smem
#define NBLK   148          // 148*14 = 2072 >= 2048
#define NTH    256          // 2 groups x 128 threads; each thread owns 2 gate rows
#define GS     9            // gsm batch stride (conflict-free)

// packed f32x2 FMA (sm_10x): acc.lo += w.lo*h.lo ; acc.hi += w.hi*h.hi
__device__ __forceinline__ void fma2(unsigned long long &acc,
                                     unsigned long long w,
                                     unsigned long long h) {
    asm("fma.rn.f32x2 %0, %1, %2, %0;" : "+l"(acc) : "l"(w), "l"(h));
}
__device__ __forceinline__ float2 unpack2(unsigned long long v) {
    float2 r;
    asm("mov.b64 {%0, %1}, %2;" : "=f"(r.x), "=f"(r.y) : "l"(v));
    return r;
}
__device__ __forceinline__ float sigf(float x) {
    return __fdividef(1.0f, 1.0f + __expf(-x));
}
__device__ __forceinline__ float tanhfast(float x) {
    float e = __expf(2.0f * x);
    return 1.0f - __fdividef(2.0f, e + 1.0f);
}
// named barrier over one group's 128 threads (warp-aligned groups)
__device__ __forceinline__ void gbar(int id) {
    asm volatile("bar.sync %0, %1;" :: "r"(id), "r"(128) : "memory");
}

__global__ void __launch_bounds__(NTH, 1)
lstm_fused_kernel(const float* __restrict__ x,      // [B, T, 1]
                  const float* __restrict__ W_ih,   // [4H, 1]
                  const float* __restrict__ W_hh,   // [4H, H]
                  const float* __restrict__ b_ih,   // [4H]
                  const float* __restrict__ b_hh,   // [4H]
                  const float* __restrict__ fc1_w,  // [16, H]
                  const float* __restrict__ fc1_b,  // [16]
                  const float* __restrict__ fc2_w,  // [1, 16]
                  const float* __restrict__ fc2_b,  // [1]
                  float* __restrict__ out)          // [B, 1]
{
    __shared__ __align__(16) float hsm[2][HB * HDIM];  // h_{t-1} per group
    __shared__ float gsm[2][G4 * GS];                  // ACTIVATED gates
    __shared__ float xs[2][HB * XC];                   // x slab per group
    __shared__ float zsm[2][HB * 16];                  // fc1 activations

    const int tid  = threadIdx.x;
    const int grp  = tid >> 7;             // 0 or 1
    const int gtid = tid & 127;            // thread-in-group
    const int bar  = grp + 1;              // named barrier id
    const int b0   = blockIdx.x * BB + grp * HB;   // first global batch of group
    const int gA   = gtid;                 // row in [0,128): i-gate or f-gate
    const int gB   = gtid + 128;           // row in [128,256): g-gate or o-gate
    const bool isG = (gtid < 64);          // gB is a tanh (cell-candidate) row

    // Two gate rows of W_hh packed into f32x2 pairs (registers).
    unsigned long long wA[HDIM / 2], wB[HDIM / 2];
    {
        const ulonglong2* wpA = reinterpret_cast<const ulonglong2*>(W_hh + gA * HDIM);
        const ulonglong2* wpB = reinterpret_cast<const ulonglong2*>(W_hh + gB * HDIM);
        #pragma unroll
        for (int i = 0; i < HDIM / 4; i++) {
            ulonglong2 vA = wpA[i];
            wA[2 * i] = vA.x;  wA[2 * i + 1] = vA.y;
            ulonglong2 vB = wpB[i];
            wB[2 * i] = vB.x;  wB[2 * i + 1] = vB.y;
        }
    }
    const float wihA  = W_ih[gA],            wihB  = W_ih[gB];
    const float biasA = b_ih[gA] + b_hh[gA], biasB = b_ih[gB] + b_hh[gB];

    for (int i = gtid; i < HB * HDIM; i += 128) hsm[grp][i] = 0.0f;
    float creg[4] = {0.0f, 0.0f, 0.0f, 0.0f};  // cell state: units gtid+128q
    gbar(bar);

    for (int t = 0; t < TLEN; t++) {
        // ---- refill x slab every XC steps (coalesced, masked) ----
        if ((t & (XC - 1)) == 0) {
            for (int m = gtid; m < HB * XC; m += 128) {
                int b  = m >> 7;
                int tt = m & (XC - 1);
                int bg = b0 + b;
                xs[grp][m] = (bg < BTOT) ? x[bg * TLEN + t + tt] : 0.0f;
            }
            gbar(bar);
        }
        const int tt = t & (XC - 1);
        const float* hp = hsm[grp];

        // ---- gate phase: dot products (fma pipe) + activations (MUFU pipe,
        //      hidden under the FFMA stream) ----
        #pragma unroll
        for (int b = 0; b < HB; b++) {
            unsigned long long a0 = 0ULL, a1 = 0ULL;
            const ulonglong2* h0 = reinterpret_cast<const ulonglong2*>(hp + b * HDIM);
            #pragma unroll
            for (int kk = 0; kk < HDIM / 4; kk++) {
                ulonglong2 p = h0[kk];      // LDS.128 broadcast
                fma2(a0, wA[2 * kk],     p.x);
                fma2(a1, wB[2 * kk],     p.x);
                fma2(a0, wA[2 * kk + 1], p.y);
                fma2(a1, wB[2 * kk + 1], p.y);
            }
            float2 f0 = unpack2(a0), f1 = unpack2(a1);
            float xv = xs[grp][b * XC + tt];
            float vA = f0.x + f0.y + xv * wihA + biasA;   // i or f pre-act
            float vB = f1.x + f1.y + xv * wihB + biasB;   // g or o pre-act
            gsm[grp][gA * GS + b] = sigf(vA);             // i/f: sigmoid
            gsm[grp][gB * GS + b] = isG ? tanhfast(vB)    // g: tanh (warp-uniform)
                                        : sigf(vB);       // o: sigmoid
        }
        gbar(bar);

        // ---- elementwise phase (tiny now): c,h update only ----
        #pragma unroll
        for (int q = 0; q < 4; q++) {
            int u = gtid + q * 128;
            if (u < HB * HDIM) {
                int b = u >> 6, j = u & 63;
                float gi = gsm[grp][j * GS + b];
                float gf = gsm[grp][(j + 64) * GS + b];
                float gc = gsm[grp][(j + 128) * GS + b];
                float go = gsm[grp][(j + 192) * GS + b];
                float cn = gf * creg[q] + gi * gc;
                creg[q] = cn;
                hsm[grp][b * HDIM + j] = go * tanhfast(cn);
            }
        }
        gbar(bar);
    }

    // ---- MLP head (per group): z = relu(h @ fc1^T + b); out = z @ fc2^T + b ----
    if (gtid < HB * 16) {
        int b = gtid >> 4, jj = gtid & 15;
        float acc = fc1_b[jj];
        const float* wr = fc1_w + jj * HDIM;
        #pragma unroll
        for (int k = 0; k < HDIM; k++) acc += hsm[grp][b * HDIM + k] * wr[k];
        zsm[grp][gtid] = fmaxf(acc, 0.0f);
    }
    gbar(bar);
    if (gtid < HB) {
        int bg = b0 + gtid;
        if (bg < BTOT) {
            float acc = fc2_b[0];
            #pragma unroll
            for (int jj = 0; jj < 16; jj++) acc += zsm[grp][gtid * 16 + jj] * fc2_w[jj];
            out[bg] = acc;
        }
    }
}

extern "C" void kernel_launch(void* const* d_in, const int* in_sizes, int n_in,
                              void* d_out, int out_size) {
    const float* x     = (const float*)d_in[0];
    const float* W_ih  = (const float*)d_in[1];
    const float* W_hh  = (const float*)d_in[2];
    const float* b_ih  = (const float*)d_in[3];
    const float* b_hh  = (const float*)d_in[4];
    const float* fc1_w = (const float*)d_in[5];
    const float* fc1_b = (const float*)d_in[6];
    const float* fc2_w = (const float*)d_in[7];
    const float* fc2_b = (const float*)d_in[8];
    float* out = (float*)d_out;

    lstm_fused_kernel<<<NBLK, NTH>>>(x, W_ih, W_hh, b_ih, b_hh,
                                     fc1_w, fc1_b, fc2_w, fc2_b, out);
}

// round 11
// speedup vs baseline: 1.2127x; 1.2127x over previous
#include <cuda_runtime.h>

// Problem constants
#define BTOT   2048
#define TLEN   512
#define HDIM   64
#define G4     256          // 4*H gates
#define BBLK   14           // batches per block
#define HB     7            // batches per group (two groups per block)
#define BA     4            // half A = batches [0,4), half B = [4,7)
#define XC     256          // x chunk length cached in smem
#define NBLK   148          // 148*14 = 2072 >= 2048
#define NTH    256          // 2 groups x 128 threads; each thread owns 2 gate rows
#define GS     9            // gsm batch stride (conflict-free)

// packed f32x2 FMA (sm_10x): acc.lo += w.lo*h.lo ; acc.hi += w.hi*h.hi
__device__ __forceinline__ void fma2(unsigned long long &acc,
                                     unsigned long long w,
                                     unsigned long long h) {
    asm("fma.rn.f32x2 %0, %1, %2, %0;" : "+l"(acc) : "l"(w), "l"(h));
}
__device__ __forceinline__ float2 unpack2(unsigned long long v) {
    float2 r;
    asm("mov.b64 {%0, %1}, %2;" : "=f"(r.x), "=f"(r.y) : "l"(v));
    return r;
}
__device__ __forceinline__ float sigf(float x) {
    return __fdividef(1.0f, 1.0f + __expf(-x));
}
__device__ __forceinline__ float tanhfast(float x) {
    float e = __expf(2.0f * x);
    return 1.0f - __fdividef(2.0f, e + 1.0f);
}
// named barrier over one group's 128 threads (warp-aligned groups)
__device__ __forceinline__ void gbar(int id) {
    asm volatile("bar.sync %0, %1;" :: "r"(id), "r"(128) : "memory");
}

// gate dot products for batches [B0,B1): fma-pipe stream
#define GATES(B0, B1, TT)                                                   \
    {                                                                       \
        _Pragma("unroll")                                                   \
        for (int b = (B0); b < (B1); b++) {                                 \
            unsigned long long a0 = 0ULL, a1 = 0ULL;                        \
            const ulonglong2* h0 =                                          \
                reinterpret_cast<const ulonglong2*>(hp + b * HDIM);         \
            _Pragma("unroll")                                               \
            for (int kk = 0; kk < HDIM / 4; kk++) {                         \
                ulonglong2 p = h0[kk];          /* LDS.128 broadcast */     \
                fma2(a0, wA[2 * kk],     p.x);                              \
                fma2(a1, wB[2 * kk],     p.x);                              \
                fma2(a0, wA[2 * kk + 1], p.y);                              \
                fma2(a1, wB[2 * kk + 1], p.y);                              \
            }                                                               \
            float2 f0 = unpack2(a0), f1 = unpack2(a1);                      \
            float xv = xsg[b * XC + (TT)];                                  \
            gsg[gA * GS + b] = f0.x + f0.y + xv * wihA + biasA;             \
            gsg[gB * GS + b] = f1.x + f1.y + xv * wihB + biasB;             \
        }                                                                   \
    }

// elementwise c/h update for units u = gtid + 128q, q in [Q0,Q1): MUFU stream
#define EWU(Q0, Q1)                                                         \
    {                                                                       \
        _Pragma("unroll")                                                   \
        for (int q = (Q0); q < (Q1); q++) {                                 \
            int u = gtid + q * 128;                                         \
            if (u < HB * HDIM) {                                            \
                int b = u >> 6, j = u & 63;                                 \
                float gi = sigf(gsg[j * GS + b]);                           \
                float gf = sigf(gsg[(j + 64) * GS + b]);                    \
                float gc = tanhfast(gsg[(j + 128) * GS + b]);               \
                float go = sigf(gsg[(j + 192) * GS + b]);                   \
                float cn = gf * creg[q] + gi * gc;                          \
                creg[q] = cn;                                               \
                hp[b * HDIM + j] = go * tanhfast(cn);                       \
            }                                                               \
        }                                                                   \
    }

__global__ void __launch_bounds__(NTH, 1)
lstm_fused_kernel(const float* __restrict__ x,      // [B, T, 1]
                  const float* __restrict__ W_ih,   // [4H, 1]
                  const float* __restrict__ W_hh,   // [4H, H]
                  const float* __restrict__ b_ih,   // [4H]
                  const float* __restrict__ b_hh,   // [4H]
                  const float* __restrict__ fc1_w,  // [16, H]
                  const float* __restrict__ fc1_b,  // [16]
                  const float* __restrict__ fc2_w,  // [1, 16]
                  const float* __restrict__ fc2_b,  // [1]
                  float* __restrict__ out)          // [B, 1]
{
    __shared__ __align__(16) float hsm[2][HB * HDIM];  // h_{t-1} per group
    __shared__ float gsm[2][G4 * GS];                  // gate pre-activations
    __shared__ float xs[2][HB * XC];                   // x slab per group
    __shared__ float zsm[2][HB * 16];                  // fc1 activations

    const int tid  = threadIdx.x;
    const int grp  = tid >> 7;             // 0 or 1
    const int gtid = tid & 127;            // thread-in-group
    const int bar  = grp + 1;              // named barrier id
    const int b0   = blockIdx.x * BBLK + grp * HB;  // first global batch
    const int gA   = gtid;                 // first owned gate row
    const int gB   = gtid + 128;           // second owned gate row

    // Two gate rows of W_hh packed into f32x2 pairs (registers).
    unsigned long long wA[HDIM / 2], wB[HDIM / 2];
    {
        const ulonglong2* wpA = reinterpret_cast<const ulonglong2*>(W_hh + gA * HDIM);
        const ulonglong2* wpB = reinterpret_cast<const ulonglong2*>(W_hh + gB * HDIM);
        #pragma unroll
        for (int i = 0; i < HDIM / 4; i++) {
            ulonglong2 vA = wpA[i];
            wA[2 * i] = vA.x;  wA[2 * i + 1] = vA.y;
            ulonglong2 vB = wpB[i];
            wB[2 * i] = vB.x;  wB[2 * i + 1] = vB.y;
        }
    }
    const float wihA  = W_ih[gA],            wihB  = W_ih[gB];
    const float biasA = b_ih[gA] + b_hh[gA], biasB = b_ih[gB] + b_hh[gB];

    float* hp  = hsm[grp];
    float* gsg = gsm[grp];
    float* xsg = xs[grp];

    for (int i = gtid; i < HB * HDIM; i += 128) hp[i] = 0.0f;
    float creg[4] = {0.0f, 0.0f, 0.0f, 0.0f};  // cell state: units gtid+128q

    // ---- prologue: load x chunk 0, then gates for half A at t=0 ----
    for (int m = gtid; m < HB * XC; m += 128) {
        int b  = m >> 8;                 // / XC
        int tt = m & (XC - 1);
        int bg = b0 + b;
        xsg[m] = (bg < BTOT) ? x[bg * TLEN + tt] : 0.0f;
    }
    gbar(bar);
    GATES(0, BA, 0);
    gbar(bar);

    // ---- main loop: two software-pipelined phases per step ----
    for (int t = 0; t < TLEN - 1; t++) {
        const int tt  = t & (XC - 1);
        const int tt1 = (t + 1) & (XC - 1);

        // phase 1: elementwise(A, t)  +  gates(B, t)
        EWU(0, 2);
        GATES(BA, HB, tt);
        gbar(bar);

        // phase 2: elementwise(B, t)  +  gates(A, t+1)
        EWU(2, 4);
        if (tt1 == 0) {                  // refill x slab (t+1 == 256 only)
            const int base = t + 1;
            for (int m = gtid; m < HB * XC; m += 128) {
                int b   = m >> 8;
                int ttt = m & (XC - 1);
                int bg  = b0 + b;
                xsg[m] = (bg < BTOT) ? x[bg * TLEN + base + ttt] : 0.0f;
            }
            gbar(bar);                   // xs visible before gates read it
        }
        GATES(0, BA, tt1);
        gbar(bar);
    }

    // ---- epilogue: finish step T-1 ----
    {
        const int tt = (TLEN - 1) & (XC - 1);
        EWU(0, 2);
        GATES(BA, HB, tt);
        gbar(bar);
        EWU(2, 4);
        gbar(bar);
    }

    // ---- MLP head (per group): z = relu(h @ fc1^T + b); out = z @ fc2^T + b ----
    if (gtid < HB * 16) {
        int b = gtid >> 4, jj = gtid & 15;
        float acc = fc1_b[jj];
        const float* wr = fc1_w + jj * HDIM;
        #pragma unroll
        for (int k = 0; k < HDIM; k++) acc += hp[b * HDIM + k] * wr[k];
        zsm[grp][gtid] = fmaxf(acc, 0.0f);
    }
    gbar(bar);
    if (gtid < HB) {
        int bg = b0 + gtid;
        if (bg < BTOT) {
            float acc = fc2_b[0];
            #pragma unroll
            for (int jj = 0; jj < 16; jj++) acc += zsm[grp][gtid * 16 + jj] * fc2_w[jj];
            out[bg] = acc;
        }
    }
}

extern "C" void kernel_launch(void* const* d_in, const int* in_sizes, int n_in,
                              void* d_out, int out_size) {
    const float* x     = (const float*)d_in[0];
    const float* W_ih  = (const float*)d_in[1];
    const float* W_hh  = (const float*)d_in[2];
    const float* b_ih  = (const float*)d_in[3];
    const float* b_hh  = (const float*)d_in[4];
    const float* fc1_w = (const float*)d_in[5];
    const float* fc1_b = (const float*)d_in[6];
    const float* fc2_w = (const float*)d_in[7];
    const float* fc2_b = (const float*)d_in[8];
    float* out = (float*)d_out;

    lstm_fused_kernel<<<NBLK, NTH>>>(x, W_ih, W_hh, b_ih, b_hh,
                                     fc1_w, fc1_b, fc2_w, fc2_b, out);
}